// round 9
// baseline (speedup 1.0000x reference)
#include <cuda_runtime.h>
#include <cstdint>

// Problem constants (fixed shapes per reference setup_inputs)
#define HW        65536          // 256*256
#define NPIX      1048576        // 16*256*256
#define SIGMA2EPS 625.00001f     // sigma^2 + eps
#define TILE_PX   256            // pixels per CTA tile
#define NBLOCKS   4096           // NPIX / TILE_PX
#define TILE_BYTES_PER_CH 1024   // 256 px * 4B
#define TILE_TX   (12 * TILE_BYTES_PER_CH)  // 12 channels

__device__ float        g_partials[NBLOCKS];
__device__ unsigned int g_ticket = 0;   // self-resetting via atomicInc wrap

// FMA-only log for positive normalized floats (cephes logf reduction).
__device__ __forceinline__ float fast_logf(float det)
{
    int bits = __float_as_int(det);
    int e = (bits >> 23) - 127;
    float m = __int_as_float((bits & 0x007FFFFF) | 0x3F800000); // [1,2)
    if (m > 1.41421356237f) { m *= 0.5f; e += 1; }              // [sqrt(.5),sqrt(2))
    float x = m - 1.0f;
    float z = x * x;
    float p =              7.0376836292e-2f;
    p = fmaf(p, x, -1.1514610310e-1f);
    p = fmaf(p, x,  1.1676998740e-1f);
    p = fmaf(p, x, -1.2420140846e-1f);
    p = fmaf(p, x,  1.4249322787e-1f);
    p = fmaf(p, x, -1.6668057665e-1f);
    p = fmaf(p, x,  2.0000714765e-1f);
    p = fmaf(p, x, -2.4999993993e-1f);
    p = fmaf(p, x,  3.3333331174e-1f);
    float y = x * z * p;
    y = fmaf(-0.5f, z, y);
    return fmaf((float)e, 0.693147180559945f, x + y);
}

__global__ __launch_bounds__(128) void loss_fused_kernel(
    const float* __restrict__ outp, const float* __restrict__ truth,
    float* __restrict__ res)
{
    __shared__ __align__(128) float tile[12 * TILE_PX];   // 12 KB
    __shared__ __align__(8)  unsigned long long mbar;
    __shared__ float sh[4];
    __shared__ bool  is_last;

    int tid = threadIdx.x;
    int cta = blockIdx.x;
    int n   = cta >> 8;                 // 256 tiles per image
    int hw  = (cta & 255) * TILE_PX;

    uint32_t smem_tile = (uint32_t)__cvta_generic_to_shared(tile);
    uint32_t smem_mbar = (uint32_t)__cvta_generic_to_shared(&mbar);

    if (tid == 0) {
        asm volatile("mbarrier.init.shared.b64 [%0], 1;" :: "r"(smem_mbar) : "memory");
        asm volatile("fence.proxy.async.shared::cta;" ::: "memory");
    }
    __syncthreads();

    if (tid == 0) {
        asm volatile("mbarrier.arrive.expect_tx.shared.b64 _, [%0], %1;"
                     :: "r"(smem_mbar), "r"((uint32_t)TILE_TX) : "memory");
        const float* osrc = outp  + (size_t)n * 9 * HW + hw;
        const float* tsrc = truth + (size_t)n * 3 * HW + hw;
        #pragma unroll
        for (int ch = 0; ch < 9; ch++) {
            asm volatile(
                "cp.async.bulk.shared::cluster.global.mbarrier::complete_tx::bytes "
                "[%0], [%1], %2, [%3];"
                :: "r"(smem_tile + ch * TILE_BYTES_PER_CH),
                   "l"(osrc + (size_t)ch * HW),
                   "r"((uint32_t)TILE_BYTES_PER_CH),
                   "r"(smem_mbar) : "memory");
        }
        #pragma unroll
        for (int ch = 0; ch < 3; ch++) {
            asm volatile(
                "cp.async.bulk.shared::cluster.global.mbarrier::complete_tx::bytes "
                "[%0], [%1], %2, [%3];"
                :: "r"(smem_tile + (9 + ch) * TILE_BYTES_PER_CH),
                   "l"(tsrc + (size_t)ch * HW),
                   "r"((uint32_t)TILE_BYTES_PER_CH),
                   "r"(smem_mbar) : "memory");
        }
    }

    // all threads wait for the full 12 KB tile (phase 0)
    {
        uint32_t done;
        asm volatile(
            "{\n\t.reg .pred p;\n\t"
            "mbarrier.try_wait.parity.shared.b64 p, [%1], %2;\n\t"
            "selp.b32 %0, 1, 0, p;\n\t}"
            : "=r"(done) : "r"(smem_mbar), "r"(0u) : "memory");
        while (!done) {
            asm volatile(
                "{\n\t.reg .pred p;\n\t"
                "mbarrier.try_wait.parity.shared.b64 p, [%1], %2;\n\t"
                "selp.b32 %0, 1, 0, p;\n\t}"
                : "=r"(done) : "r"(smem_mbar), "r"(0u) : "memory");
        }
    }

    // ---- compute: 2 pixels per thread from SMEM
    float acc = 0.0f;
    int px = tid * 2;
    {
        float2 m0 = *(const float2*)&tile[ 0*TILE_PX + px];
        float2 m1 = *(const float2*)&tile[ 1*TILE_PX + px];
        float2 m2 = *(const float2*)&tile[ 2*TILE_PX + px];
        float2 va = *(const float2*)&tile[ 3*TILE_PX + px];
        float2 vb = *(const float2*)&tile[ 4*TILE_PX + px];
        float2 vc = *(const float2*)&tile[ 5*TILE_PX + px];
        float2 vd = *(const float2*)&tile[ 6*TILE_PX + px];
        float2 ve = *(const float2*)&tile[ 7*TILE_PX + px];
        float2 vf = *(const float2*)&tile[ 8*TILE_PX + px];
        float2 t0 = *(const float2*)&tile[ 9*TILE_PX + px];
        float2 t1 = *(const float2*)&tile[10*TILE_PX + px];
        float2 t2 = *(const float2*)&tile[11*TILE_PX + px];

        const float* pm0 = (const float*)&m0; const float* pm1 = (const float*)&m1;
        const float* pm2 = (const float*)&m2;
        const float* pa  = (const float*)&va; const float* pb  = (const float*)&vb;
        const float* pc  = (const float*)&vc; const float* pd  = (const float*)&vd;
        const float* pe  = (const float*)&ve; const float* pf  = (const float*)&vf;
        const float* pt0 = (const float*)&t0; const float* pt1 = (const float*)&t1;
        const float* pt2 = (const float*)&t2;

        #pragma unroll
        for (int k = 0; k < 2; k++) {
            float a = pa[k], b = pb[k], c = pc[k];
            float d = pd[k], e = pe[k], f = pf[k];
            float d0 = pt0[k] - pm0[k];
            float d1 = pt1[k] - pm1[k];
            float d2 = pt2[k] - pm2[k];

            // A = [[a,b,c],[d,e,0],[f,0,0]];  V = A^T A + (sigma^2+eps) I
            float V00 = fmaf(a, a, fmaf(d, d, fmaf(f, f, SIGMA2EPS)));
            float V01 = fmaf(a, b, d * e);
            float V02 = a * c;
            float V11 = fmaf(b, b, fmaf(e, e, SIGMA2EPS));
            float V12 = b * c;
            float V22 = fmaf(c, c, SIGMA2EPS);

            // Adjugate (symmetric)
            float M00 = fmaf(V11, V22, -V12 * V12);
            float M01 = fmaf(V02, V12, -V01 * V22);
            float M02 = fmaf(V01, V12, -V02 * V11);
            float M11 = fmaf(V00, V22, -V02 * V02);
            float M12 = fmaf(V01, V02, -V00 * V12);
            float M22 = fmaf(V00, V11, -V01 * V01);

            float det = fmaf(V00, M00, fmaf(V01, M01, V02 * M02));

            // quad numerator: d^T adj(V) d
            float qn = d0 * d0 * M00;
            qn = fmaf(d1 * d1, M11, qn);
            qn = fmaf(d2 * d2, M22, qn);
            float cross = d0 * d1 * M01;
            cross = fmaf(d0 * d2, M02, cross);
            cross = fmaf(d1 * d2, M12, cross);
            qn = fmaf(2.0f, cross, qn);

            // likelihood = 0.5*(qn/det + log(det)); det >= sigma^6 ~ 2.4e8 > 0
            acc += __fdividef(qn, det) + fast_logf(det);
        }
    }
    acc *= 0.5f;

    // ---- block reduction (4 warps)
    #pragma unroll
    for (int o = 16; o; o >>= 1)
        acc += __shfl_xor_sync(0xFFFFFFFFu, acc, o);

    if ((tid & 31) == 0) sh[tid >> 5] = acc;
    __syncthreads();
    if (tid < 4) {
        float v = sh[tid];
        v += __shfl_xor_sync(0xFu, v, 2);
        v += __shfl_xor_sync(0xFu, v, 1);
        if (tid == 0) {
            __stcg(&g_partials[blockIdx.x], v);
            __threadfence();
            unsigned t = atomicInc(&g_ticket, NBLOCKS - 1); // wraps to 0 -> self reset
            is_last = (t == NBLOCKS - 1);
        }
    }
    __syncthreads();

    // ---- last block: deterministic fixed-order final reduction of 4096 partials
    if (is_last) {
        float v = 0.0f;
        #pragma unroll
        for (int j = 0; j < 32; j++)
            v += __ldcg(&g_partials[tid + j * 128]);
        #pragma unroll
        for (int o = 16; o; o >>= 1)
            v += __shfl_xor_sync(0xFFFFFFFFu, v, o);
        if ((tid & 31) == 0) sh[tid >> 5] = v;
        __syncthreads();
        if (tid < 4) {
            float x = sh[tid];
            x += __shfl_xor_sync(0xFu, x, 2);
            x += __shfl_xor_sync(0xFu, x, 1);
            if (tid == 0) res[0] = x * (1.0f / (float)NPIX) - 2.5f;
        }
    }
}

extern "C" void kernel_launch(void* const* d_in, const int* in_sizes, int n_in,
                              void* d_out, int out_size)
{
    const float* outp  = (const float*)d_in[0];  // (16, 9, 256, 256) f32
    const float* truth = (const float*)d_in[1];  // (16, 3, 256, 256) f32
    float* res = (float*)d_out;

    loss_fused_kernel<<<NBLOCKS, 128>>>(outp, truth, res);
}

// round 10
// speedup vs baseline: 1.1633x; 1.1633x over previous
#include <cuda_runtime.h>
#include <cstdint>

// Problem constants (fixed shapes per reference setup_inputs)
#define HW        65536          // 256*256
#define NPIX      1048576        // 16*256*256
#define SIGMA2EPS 625.00001f     // sigma^2 + eps
#define NBLOCKS   2048           // CTAs (128 threads each), 2 float2-items/thread
#define NTHREADS  262144         // NBLOCKS * 128

__device__ float        g_partials[NBLOCKS];
__device__ unsigned int g_ticket = 0;   // self-resetting via atomicInc wrap

// read-only float2 load with 256B L2 prefetch granule
__device__ __forceinline__ float2 ldg_nc_256(const float2* p)
{
    float2 r;
    asm volatile("ld.global.nc.L2::256B.v2.f32 {%0, %1}, [%2];"
                 : "=f"(r.x), "=f"(r.y) : "l"(p));
    return r;
}

// FMA-only log for positive normalized floats (cephes logf reduction).
__device__ __forceinline__ float fast_logf(float det)
{
    int bits = __float_as_int(det);
    int e = (bits >> 23) - 127;
    float m = __int_as_float((bits & 0x007FFFFF) | 0x3F800000); // [1,2)
    if (m > 1.41421356237f) { m *= 0.5f; e += 1; }              // [sqrt(.5),sqrt(2))
    float x = m - 1.0f;
    float z = x * x;
    float p =              7.0376836292e-2f;
    p = fmaf(p, x, -1.1514610310e-1f);
    p = fmaf(p, x,  1.1676998740e-1f);
    p = fmaf(p, x, -1.2420140846e-1f);
    p = fmaf(p, x,  1.4249322787e-1f);
    p = fmaf(p, x, -1.6668057665e-1f);
    p = fmaf(p, x,  2.0000714765e-1f);
    p = fmaf(p, x, -2.4999993993e-1f);
    p = fmaf(p, x,  3.3333331174e-1f);
    float y = x * z * p;
    y = fmaf(-0.5f, z, y);
    return fmaf((float)e, 0.693147180559945f, x + y);
}

__global__ __launch_bounds__(128) void loss_fused_kernel(
    const float* __restrict__ outp, const float* __restrict__ truth,
    float* __restrict__ res)
{
    int T = blockIdx.x * 128 + threadIdx.x;   // global thread id

    float acc = 0.0f;

    #pragma unroll 1
    for (int it = 0; it < 2; ++it) {
        int i   = T + it * NTHREADS;          // float2-item index
        int pix = i << 1;                     // first pixel of the pair
        int n   = pix >> 16;                  // image index
        int hw  = pix & 65535;

        const float2* ob = (const float2*)(outp  + (size_t)n * 9 * HW + hw);
        const float2* tb = (const float2*)(truth + (size_t)n * 3 * HW + hw);
        const int CS = HW / 2;                // channel stride in float2 units

        // All 12 independent loads front-batched; 256B L2 prefetch granules
        float2 m0 = ldg_nc_256(ob + 0*CS);
        float2 m1 = ldg_nc_256(ob + 1*CS);
        float2 m2 = ldg_nc_256(ob + 2*CS);
        float2 va = ldg_nc_256(ob + 3*CS);
        float2 vb = ldg_nc_256(ob + 4*CS);
        float2 vc = ldg_nc_256(ob + 5*CS);
        float2 vd = ldg_nc_256(ob + 6*CS);
        float2 ve = ldg_nc_256(ob + 7*CS);
        float2 vf = ldg_nc_256(ob + 8*CS);
        float2 t0 = ldg_nc_256(tb + 0*CS);
        float2 t1 = ldg_nc_256(tb + 1*CS);
        float2 t2 = ldg_nc_256(tb + 2*CS);

        const float* pm0 = (const float*)&m0; const float* pm1 = (const float*)&m1;
        const float* pm2 = (const float*)&m2;
        const float* pa  = (const float*)&va; const float* pb  = (const float*)&vb;
        const float* pc  = (const float*)&vc; const float* pd  = (const float*)&vd;
        const float* pe  = (const float*)&ve; const float* pf  = (const float*)&vf;
        const float* pt0 = (const float*)&t0; const float* pt1 = (const float*)&t1;
        const float* pt2 = (const float*)&t2;

        #pragma unroll
        for (int k = 0; k < 2; k++) {
            float a = pa[k], b = pb[k], c = pc[k];
            float d = pd[k], e = pe[k], f = pf[k];
            float d0 = pt0[k] - pm0[k];
            float d1 = pt1[k] - pm1[k];
            float d2 = pt2[k] - pm2[k];

            // A = [[a,b,c],[d,e,0],[f,0,0]];  V = A^T A + (sigma^2+eps) I
            float V00 = fmaf(a, a, fmaf(d, d, fmaf(f, f, SIGMA2EPS)));
            float V01 = fmaf(a, b, d * e);
            float V02 = a * c;
            float V11 = fmaf(b, b, fmaf(e, e, SIGMA2EPS));
            float V12 = b * c;
            float V22 = fmaf(c, c, SIGMA2EPS);

            // Adjugate (symmetric)
            float M00 = fmaf(V11, V22, -V12 * V12);
            float M01 = fmaf(V02, V12, -V01 * V22);
            float M02 = fmaf(V01, V12, -V02 * V11);
            float M11 = fmaf(V00, V22, -V02 * V02);
            float M12 = fmaf(V01, V02, -V00 * V12);
            float M22 = fmaf(V00, V11, -V01 * V01);

            float det = fmaf(V00, M00, fmaf(V01, M01, V02 * M02));

            // quad numerator: d^T adj(V) d
            float qn = d0 * d0 * M00;
            qn = fmaf(d1 * d1, M11, qn);
            qn = fmaf(d2 * d2, M22, qn);
            float cross = d0 * d1 * M01;
            cross = fmaf(d0 * d2, M02, cross);
            cross = fmaf(d1 * d2, M12, cross);
            qn = fmaf(2.0f, cross, qn);

            // likelihood = 0.5*(qn/det + log(det)); det >= sigma^6 ~ 2.4e8 > 0
            acc += __fdividef(qn, det) + fast_logf(det);
        }
    }
    acc *= 0.5f;

    // ---- block reduction (4 warps)
    #pragma unroll
    for (int o = 16; o; o >>= 1)
        acc += __shfl_xor_sync(0xFFFFFFFFu, acc, o);

    __shared__ float sh[4];
    __shared__ bool  is_last;
    if ((threadIdx.x & 31) == 0) sh[threadIdx.x >> 5] = acc;
    __syncthreads();
    if (threadIdx.x < 4) {
        float v = sh[threadIdx.x];
        v += __shfl_xor_sync(0xFu, v, 2);
        v += __shfl_xor_sync(0xFu, v, 1);
        if (threadIdx.x == 0) {
            __stcg(&g_partials[blockIdx.x], v);
            __threadfence();
            unsigned t = atomicInc(&g_ticket, NBLOCKS - 1); // wraps to 0 -> self reset
            is_last = (t == NBLOCKS - 1);
        }
    }
    __syncthreads();

    // ---- last block: deterministic fixed-order final reduction of 2048 partials
    if (is_last) {
        int t = threadIdx.x;
        float v = 0.0f;
        #pragma unroll
        for (int j = 0; j < 16; j++)
            v += __ldcg(&g_partials[t + j * 128]);
        #pragma unroll
        for (int o = 16; o; o >>= 1)
            v += __shfl_xor_sync(0xFFFFFFFFu, v, o);
        if ((t & 31) == 0) sh[t >> 5] = v;
        __syncthreads();
        if (t < 4) {
            float x = sh[t];
            x += __shfl_xor_sync(0xFu, x, 2);
            x += __shfl_xor_sync(0xFu, x, 1);
            if (t == 0) res[0] = x * (1.0f / (float)NPIX) - 2.5f;
        }
    }
}

extern "C" void kernel_launch(void* const* d_in, const int* in_sizes, int n_in,
                              void* d_out, int out_size)
{
    const float* outp  = (const float*)d_in[0];  // (16, 9, 256, 256) f32
    const float* truth = (const float*)d_in[1];  // (16, 3, 256, 256) f32
    float* res = (float*)d_out;

    loss_fused_kernel<<<NBLOCKS, 128>>>(outp, truth, res);
}